// round 15
// baseline (speedup 1.0000x reference)
#include <cuda_runtime.h>
#include <cuda_bf16.h>
#include <mma.h>
#include <math.h>
#include <stdint.h>

using namespace nvcuda;

#define NDET 256
#define MTRK 256
#define VN   512
#define PPTS 512
#define TSTE 10

typedef unsigned long long ull;

__device__ __forceinline__ void fma2(ull &d, ull a, ull b) {
    asm("fma.rn.f32x2 %0, %1, %2, %0;" : "+l"(d) : "l"(a), "l"(b));
}
__device__ __forceinline__ ull pack2(float x, float y) {
    ull r; asm("mov.b64 %0, {%1, %2};" : "=l"(r) : "f"(x), "f"(y)); return r;
}
__device__ __forceinline__ float2 unpack2(ull v) {
    float2 r; asm("mov.b64 {%0, %1}, %2;" : "=f"(r.x), "=f"(r.y) : "l"(v)); return r;
}
__device__ __forceinline__ float ex2a(float x) { float y; asm("ex2.approx.f32 %0, %1;" : "=f"(y) : "f"(x)); return y; }
__device__ __forceinline__ float rcpa(float x) { float y; asm("rcp.approx.f32 %0, %1;" : "=f"(y) : "f"(x)); return y; }
__device__ __forceinline__ float sigmf(float x) { return rcpa(1.f + ex2a(-1.4426950408889634f * x)); }
__device__ __forceinline__ float tanha(float x) { float y; asm("tanh.approx.f32 %0, %1;" : "=f"(y) : "f"(x)); return y; }
__device__ __forceinline__ float sigt(float x) { return fmaf(tanha(0.5f*x), 0.5f, 0.5f); }
__device__ __forceinline__ uint32_t cvt2bf(float v_even, float v_odd) {
    uint32_t r; asm("cvt.rn.bf16x2.f32 %0, %1, %2;" : "=r"(r) : "f"(v_odd), "f"(v_even)); return r;
}

// ---------------- device scratch ----------------
__device__ float g_h[VN*128];
__device__ float g_Th[VN*128];
__device__ float g_Q[2][VN*128];
__device__ float g_P[NDET*64];
__device__ __nv_bfloat16 g_WH[4*256*128];
__device__ __nv_bfloat16 g_WL[4*256*128];
__device__ float g_bsum[4*128];
__device__ float g_w1p[64*128];
__device__ unsigned g_mask[VN*16];
__device__ float g_epart[VN*4*128];
// pointnet pre-split weights (global, L1/L2-resident)
__device__ __nv_bfloat16 g_W2H[8192], g_W2L[8192];   // [j][k] ld 64
__device__ __nv_bfloat16 g_W3H[8192], g_W3L[8192];   // [o][k] ld 128
// lstm pre-packed weights (permuted r' = u*4 + g)
__device__ float g_Wih0p[4096];    // [c/2][r'][2], c 0..7
__device__ float g_Wih0s[256];
__device__ float g_Whh0p[16384];
__device__ float g_Wih1p[16384];
__device__ float g_Whh1p[16384];
__device__ float g_LB0[256], g_LB1[256];

__device__ __forceinline__ void bfsplit(float v, __nv_bfloat16 &hb, __nv_bfloat16 &lb) {
    hb = __float2bfloat16(v);
    lb = __float2bfloat16(v - __bfloat162float(hb));
}

// ---------------- presplit: pointnet + lstm weight prepack (before mega) ----------------
__global__ void presplit_kernel(const float* w2, const float* w3,
                                const float* wih0, const float* whh0,
                                const float* bih0, const float* bhh0,
                                const float* wih1, const float* whh1,
                                const float* bih1, const float* bhh1) {
    int idx = blockIdx.x*blockDim.x + threadIdx.x;
    int stride = gridDim.x*blockDim.x;
    for (int i = idx; i < 8192; i += stride) {
        __nv_bfloat16 hb, lb; bfsplit(w2[i], hb, lb);
        g_W2H[i] = hb; g_W2L[i] = lb;     // [j][k] natural layout, ld 64
    }
    for (int i = idx; i < 8192; i += stride) {
        __nv_bfloat16 hb, lb; bfsplit(w3[i], hb, lb);
        g_W3H[i] = hb; g_W3L[i] = lb;     // [o][k] natural layout, ld 128
    }
    for (int i = idx; i < 2304; i += stride) {
        int R = i/9, c = i%9; float v = wih0[i];
        int rp = (R & 63)*4 + (R >> 6);
        if (c < 8) g_Wih0p[((c>>1)*256 + rp)*2 + (c&1)] = v; else g_Wih0s[rp] = v;
    }
    for (int i = idx; i < 16384; i += stride) {
        int R = i>>6, k = i&63; int rp = (R & 63)*4 + (R >> 6);
        g_Whh0p[((k>>1)*256 + rp)*2 + (k&1)] = whh0[i];
    }
    for (int i = idx; i < 16384; i += stride) {
        int R = i>>6, k = i&63; int rp = (R & 63)*4 + (R >> 6);
        g_Wih1p[((k>>1)*256 + rp)*2 + (k&1)] = wih1[i];
    }
    for (int i = idx; i < 16384; i += stride) {
        int R = i>>6, k = i&63; int rp = (R & 63)*4 + (R >> 6);
        g_Whh1p[((k>>1)*256 + rp)*2 + (k&1)] = whh1[i];
    }
    for (int R = idx; R < 256; R += stride) {
        int rp = (R & 63)*4 + (R >> 6);
        g_LB0[rp] = bih0[R] + bhh0[R];
        g_LB1[rp] = bih1[R] + bhh1[R];
    }
}

// ---------------- prep body (thq weights etc., inside mega) ----------------
__device__ void prep_body(int pbid, const float* gc_wt, const float* gc_bt,
                          const float* gc_wp, const float* gc_bp,
                          const float* er_w1, const int* adj) {
    int idx = pbid*256 + threadIdx.x;
    int stride = 256*256;
    for (int i = idx; i < 4*256*128; i += stride) {
        int l = i >> 15, j = (i >> 7) & 255, k = i & 127;
        float v;
        if (j < 128) v = gc_wt[l*16384 + j*128 + k];
        else {
            int jj = j - 128;
            v = gc_wp[l*16384 + jj*128 + k] - gc_wt[l*16384 + jj*128 + k];
        }
        __nv_bfloat16 hb, lb; bfsplit(v, hb, lb);
        g_WH[i] = hb; g_WL[i] = lb;
    }
    for (int i = idx; i < 4*128; i += stride) g_bsum[i] = gc_bt[i] + gc_bp[i];
    for (int i = idx; i < 64*128; i += stride) {
        int r = i >> 7, k = i & 127;
        g_w1p[((k >> 1)*64 + r)*2 + (k & 1)] = er_w1[i];
    }
    for (int w = idx; w < VN*16; w += stride) {
        int i = w >> 4, wo = w & 15;
        unsigned bits = 0;
        #pragma unroll
        for (int b = 0; b < 32; b++) {
            int j = wo*32 + b;
            if (adj[j*VN + i] != 0 || j == i) bits |= (1u << b);
        }
        g_mask[w] = bits;
    }
}

// ---------------- PointNet smem layout (bytes): A buffers + aux only ----------------
#define PN_A1H   0
#define PN_A1L   18432
#define PN_A2H   36864
#define PN_A2L   71680
#define PN_AUX   106496

#define LDA1 72
#define LDA2 136

#define MEGA_SMEM 110592

// ---------------- pointnet body: B fragments from global ----------------
__device__ void pointnet_body(char* smc, int item,
                              const float* det_pts, const float* trk_pts,
                              const float* w1, const float* b1,
                              const float* b2, const float* b3) {
    __nv_bfloat16* A1H = (__nv_bfloat16*)(smc + PN_A1H);
    __nv_bfloat16* A1L = (__nv_bfloat16*)(smc + PN_A1L);
    __nv_bfloat16* A2H = (__nv_bfloat16*)(smc + PN_A2H);
    __nv_bfloat16* A2L = (__nv_bfloat16*)(smc + PN_A2L);
    float* sW1 = (float*)(smc + PN_AUX);
    float* sB1 = sW1 + 320;
    float* sB2 = sB1 + 64;
    float* sRED = sB2 + 128;

    int tid = threadIdx.x, warp = tid >> 5, lane = tid & 31;
    const float* pts = (item < NDET) ? det_pts + (size_t)item*PPTS*5
                                     : trk_pts + (size_t)(item-NDET)*PPTS*5;

    for (int i = tid; i < 320; i += 256) { int o = i/5, c = i%5; sW1[c*64+o] = w1[i]; }
    if (tid < 64)  sB1[tid] = b1[tid];
    if (tid < 128) sB2[tid] = b2[tid];
    __syncthreads();

    int rbase = lane >> 2, cbase = (lane & 3)*2;
    int r2 = warp >> 1, c2 = warp & 1;
    int band = warp*16;
    float cm[4][4];
    #pragma unroll
    for (int nt = 0; nt < 4; nt++)
        #pragma unroll
        for (int q = 0; q < 4; q++) cm[nt][q] = -3.4e38f;

    for (int t = 0; t < 4; t++) {
        {
            int rrow = lane & 15, rcolh = lane >> 4;
            const float* xp = pts + (size_t)(t*128 + band + rrow)*5;
            float x0 = xp[0], x1 = xp[1], x2 = xp[2], x3 = xp[3], x4 = xp[4];
            int ob = rcolh*32;
            int rowb = (band + rrow)*LDA1;
            #pragma unroll
            for (int o2 = 0; o2 < 16; o2++) {
                int o = ob + 2*o2;
                float v0 = sB1[o]   + x0*sW1[o]     + x1*sW1[64+o]     + x2*sW1[128+o]
                                    + x3*sW1[192+o] + x4*sW1[256+o];
                float v1 = sB1[o+1] + x0*sW1[o+1]   + x1*sW1[64+o+1]   + x2*sW1[128+o+1]
                                    + x3*sW1[192+o+1] + x4*sW1[256+o+1];
                v0 = fmaxf(v0, 0.f); v1 = fmaxf(v1, 0.f);
                uint32_t hp = cvt2bf(v0, v1);
                float h0 = __uint_as_float(hp << 16);
                float h1 = __uint_as_float(hp & 0xffff0000u);
                uint32_t lp = cvt2bf(v0 - h0, v1 - h1);
                *(uint32_t*)&A1H[rowb + o] = hp;
                *(uint32_t*)&A1L[rowb + o] = lp;
            }
        }
        __syncthreads();
        // ---- L2: rows 32*r2..+31, cols c2*64..+63; B from global ----
        {
            wmma::fragment<wmma::matrix_a, 16, 16, 16, __nv_bfloat16, wmma::row_major> Ah[2][4], Al[2][4];
            #pragma unroll
            for (int m2 = 0; m2 < 2; m2++)
                #pragma unroll
                for (int k = 0; k < 4; k++) {
                    wmma::load_matrix_sync(Ah[m2][k], &A1H[(32*r2 + 16*m2)*LDA1 + k*16], LDA1);
                    wmma::load_matrix_sync(Al[m2][k], &A1L[(32*r2 + 16*m2)*LDA1 + k*16], LDA1);
                }
            #pragma unroll
            for (int j = 0; j < 4; j++) {
                int jg = c2*64 + j*16;
                wmma::fragment<wmma::matrix_b, 16, 16, 16, __nv_bfloat16, wmma::col_major> Bh[4], Bl[4];
                #pragma unroll
                for (int k = 0; k < 4; k++) {
                    wmma::load_matrix_sync(Bh[k], &g_W2H[jg*64 + k*16], 64);
                    wmma::load_matrix_sync(Bl[k], &g_W2L[jg*64 + k*16], 64);
                }
                #pragma unroll
                for (int m2 = 0; m2 < 2; m2++) {
                    wmma::fragment<wmma::accumulator, 16, 16, 16, float> C;
                    wmma::fill_fragment(C, 0.f);
                    #pragma unroll
                    for (int k = 0; k < 4; k++) {
                        wmma::mma_sync(C, Ah[m2][k], Bh[k], C);
                        wmma::mma_sync(C, Al[m2][k], Bh[k], C);
                        wmma::mma_sync(C, Ah[m2][k], Bl[k], C);
                    }
                    int rowg0 = 32*r2 + 16*m2 + rbase;
                    #pragma unroll
                    for (int p = 0; p < 4; p++) {
                        int i0 = p*2;
                        int row = rowg0 + 8*((i0 >> 1) & 1);
                        int col = jg + cbase + 8*(i0 >> 2);
                        float v0 = fmaxf(C.x[i0]   + sB2[col],     0.f);
                        float v1 = fmaxf(C.x[i0+1] + sB2[col + 1], 0.f);
                        uint32_t hp = cvt2bf(v0, v1);
                        float h0 = __uint_as_float(hp << 16);
                        float h1 = __uint_as_float(hp & 0xffff0000u);
                        uint32_t lp = cvt2bf(v0 - h0, v1 - h1);
                        *(uint32_t*)&A2H[row*LDA2 + col] = hp;
                        *(uint32_t*)&A2L[row*LDA2 + col] = lp;
                    }
                }
            }
        }
        __syncthreads();
        // ---- L3: band rows, all 64 cols; B from global ----
        {
            wmma::fragment<wmma::matrix_a, 16, 16, 16, __nv_bfloat16, wmma::row_major> Ah[8], Al[8];
            #pragma unroll
            for (int k = 0; k < 8; k++) {
                wmma::load_matrix_sync(Ah[k], &A2H[band*LDA2 + k*16], LDA2);
                wmma::load_matrix_sync(Al[k], &A2L[band*LDA2 + k*16], LDA2);
            }
            #pragma unroll
            for (int nt = 0; nt < 4; nt++) {
                wmma::fragment<wmma::accumulator, 16, 16, 16, float> C;
                wmma::fill_fragment(C, 0.f);
                #pragma unroll
                for (int k = 0; k < 8; k++) {
                    wmma::fragment<wmma::matrix_b, 16, 16, 16, __nv_bfloat16, wmma::col_major> Bh, Bl;
                    wmma::load_matrix_sync(Bh, &g_W3H[nt*16*128 + k*16], 128);
                    wmma::load_matrix_sync(Bl, &g_W3L[nt*16*128 + k*16], 128);
                    wmma::mma_sync(C, Ah[k], Bh, C);
                    wmma::mma_sync(C, Al[k], Bh, C);
                    wmma::mma_sync(C, Ah[k], Bl, C);
                }
                cm[nt][0] = fmaxf(cm[nt][0], fmaxf(C.x[0], C.x[2]));
                cm[nt][1] = fmaxf(cm[nt][1], fmaxf(C.x[1], C.x[3]));
                cm[nt][2] = fmaxf(cm[nt][2], fmaxf(C.x[4], C.x[6]));
                cm[nt][3] = fmaxf(cm[nt][3], fmaxf(C.x[5], C.x[7]));
            }
        }
        __syncthreads();
    }
    #pragma unroll
    for (int nt = 0; nt < 4; nt++)
        #pragma unroll
        for (int q = 0; q < 4; q++) {
            float v = cm[nt][q];
            v = fmaxf(v, __shfl_xor_sync(0xffffffffu, v, 4));
            v = fmaxf(v, __shfl_xor_sync(0xffffffffu, v, 8));
            v = fmaxf(v, __shfl_xor_sync(0xffffffffu, v, 16));
            cm[nt][q] = v;
        }
    if (lane < 4) {
        #pragma unroll
        for (int nt = 0; nt < 4; nt++) {
            sRED[warp*64 + nt*16 + lane*2]     = cm[nt][0];
            sRED[warp*64 + nt*16 + lane*2 + 1] = cm[nt][1];
            sRED[warp*64 + nt*16 + lane*2 + 8] = cm[nt][2];
            sRED[warp*64 + nt*16 + lane*2 + 9] = cm[nt][3];
        }
    }
    __syncthreads();
    if (tid < 64) {
        float m = sRED[tid];
        #pragma unroll
        for (int w = 1; w < 8; w++) m = fmaxf(m, sRED[w*64 + tid]);
        g_h[item*128 + tid] = m + b3[tid];
    }
}

// ---------------- lstm body: global weights, shfl gates, 1 barrier/step ----------------
__device__ void lstm_body(char* smc, int bid, const float* tb) {
    float* sm = (float*)smc;
    float* sX   = sm;          // [2][10][10]
    float* sHa  = sm + 200;    // [2][64]
    float* sHb  = sm + 328;    // [2][64]
    float* sHs0 = sm + 456;    // [2][10][64]

    int tid = threadIdx.x;
    int m0 = bid*2;

    for (int i = tid; i < 180; i += 256) {
        int tr = i/90, rest = i%90, t = rest/9, c = rest%9;
        sX[tr*100 + t*10 + c] = tb[(size_t)(m0+tr)*TSTE*9 + t*9 + c];
    }
    if (tid < 128) sHa[tid] = 0.f;
    __syncthreads();

    int r = tid, u = r >> 2, g = r & 3;
    int lbase = (tid & 31) & ~3;
    float b0r = g_LB0[r], b1r = g_LB1[r];
    float w0s = g_Wih0s[r];
    const ull* Wih0 = (const ull*)g_Wih0p;
    const ull* Whh0 = (const ull*)g_Whh0p;
    const ull* Wih1 = (const ull*)g_Wih1p;
    const ull* Whh1 = (const ull*)g_Whh1p;
    float cc0 = 0.f, cc1 = 0.f, hn0 = 0.f, hn1 = 0.f;
    float* sHr = sHa;
    float* sHw = sHb;

    for (int t = 0; t < TSTE; t++) {
        ull a0 = 0ULL, a1 = 0ULL;
        const float* xb0 = sX + t*10;
        const float* xb1 = sX + 100 + t*10;
        #pragma unroll
        for (int c2 = 0; c2 < 4; c2++) {
            ull w = Wih0[c2*256 + r];
            fma2(a0, *(const ull*)&xb0[2*c2], w);
            fma2(a1, *(const ull*)&xb1[2*c2], w);
        }
        float s0 = xb0[8]*w0s, s1 = xb1[8]*w0s;
        #pragma unroll 8
        for (int k2 = 0; k2 < 32; k2++) {
            ull w = Whh0[k2*256 + r];
            fma2(a0, *(const ull*)&sHr[2*k2], w);
            fma2(a1, *(const ull*)&sHr[64 + 2*k2], w);
        }
        float2 p0 = unpack2(a0), p1 = unpack2(a1);
        float v0 = p0.x + p0.y + s0 + b0r;
        float v1 = p1.x + p1.y + s1 + b0r;
        float q00 = __shfl_sync(0xffffffffu, v0, lbase + 0);
        float q01 = __shfl_sync(0xffffffffu, v0, lbase + 1);
        float q02 = __shfl_sync(0xffffffffu, v0, lbase + 2);
        float q03 = __shfl_sync(0xffffffffu, v0, lbase + 3);
        float q10 = __shfl_sync(0xffffffffu, v1, lbase + 0);
        float q11 = __shfl_sync(0xffffffffu, v1, lbase + 1);
        float q12 = __shfl_sync(0xffffffffu, v1, lbase + 2);
        float q13 = __shfl_sync(0xffffffffu, v1, lbase + 3);
        cc0 = sigt(q01)*cc0 + sigt(q00)*tanha(q02);
        hn0 = sigt(q03)*tanha(cc0);
        cc1 = sigt(q11)*cc1 + sigt(q10)*tanha(q12);
        hn1 = sigt(q13)*tanha(cc1);
        if (g == 0) {
            sHw[u] = hn0; sHw[64 + u] = hn1;
            sHs0[t*64 + u] = hn0; sHs0[640 + t*64 + u] = hn1;
        }
        __syncthreads();
        float* tmp = sHr; sHr = sHw; sHw = tmp;
    }
    if (tid < 128) sHr[tid] = 0.f;
    cc0 = 0.f; cc1 = 0.f;
    __syncthreads();
    for (int t = 0; t < TSTE; t++) {
        ull a0 = 0ULL, a1 = 0ULL;
        #pragma unroll 8
        for (int k2 = 0; k2 < 32; k2++) {
            ull w = Wih1[k2*256 + r];
            fma2(a0, *(const ull*)&sHs0[t*64 + 2*k2], w);
            fma2(a1, *(const ull*)&sHs0[640 + t*64 + 2*k2], w);
        }
        #pragma unroll 8
        for (int k2 = 0; k2 < 32; k2++) {
            ull w = Whh1[k2*256 + r];
            fma2(a0, *(const ull*)&sHr[2*k2], w);
            fma2(a1, *(const ull*)&sHr[64 + 2*k2], w);
        }
        float2 p0 = unpack2(a0), p1 = unpack2(a1);
        float v0 = p0.x + p0.y + b1r;
        float v1 = p1.x + p1.y + b1r;
        float q00 = __shfl_sync(0xffffffffu, v0, lbase + 0);
        float q01 = __shfl_sync(0xffffffffu, v0, lbase + 1);
        float q02 = __shfl_sync(0xffffffffu, v0, lbase + 2);
        float q03 = __shfl_sync(0xffffffffu, v0, lbase + 3);
        float q10 = __shfl_sync(0xffffffffu, v1, lbase + 0);
        float q11 = __shfl_sync(0xffffffffu, v1, lbase + 1);
        float q12 = __shfl_sync(0xffffffffu, v1, lbase + 2);
        float q13 = __shfl_sync(0xffffffffu, v1, lbase + 3);
        cc0 = sigt(q01)*cc0 + sigt(q00)*tanha(q02);
        hn0 = sigt(q03)*tanha(cc0);
        cc1 = sigt(q11)*cc1 + sigt(q10)*tanha(q12);
        hn1 = sigt(q13)*tanha(cc1);
        if (g == 0) { sHw[u] = hn0; sHw[64 + u] = hn1; }
        __syncthreads();
        float* tmp = sHr; sHr = sHw; sHw = tmp;
    }
    if (g == 0) {
        g_h[(NDET + m0 + 0)*128 + 64 + u] = hn0;
        g_h[(NDET + m0 + 1)*128 + 64 + u] = hn1;
    }
}

// ---------------- detmot body ----------------
__device__ void detmot_body(const float* boxes, const float* w1, const float* b1,
                            const float* w2, const float* b2) {
    int i = threadIdx.x;
    float x[9];
    #pragma unroll
    for (int c = 0; c < 9; c++) x[c] = boxes[i*9 + c];
    float h[32];
    #pragma unroll
    for (int r = 0; r < 32; r++) {
        float a = b1[r];
        #pragma unroll
        for (int c = 0; c < 9; c++) a += x[c]*w1[r*9 + c];
        h[r] = fmaxf(a, 0.f);
    }
    for (int o = 0; o < 64; o++) {
        float a = b2[o];
        #pragma unroll
        for (int r = 0; r < 32; r++) a += h[r]*w2[o*32 + r];
        g_h[i*128 + 64 + o] = a;
    }
}

// ---------------- mega kernel ----------------
__global__ __launch_bounds__(256, 2) void mega_kernel(
    const float* det_pts, const float* trk_pts,
    const float* pn_w1, const float* pn_b1, const float* pn_b2, const float* pn_b3,
    const float* det_boxes, const float* dm_w1, const float* dm_b1,
    const float* dm_w2, const float* dm_b2,
    const float* tb,
    const float* gc_wt, const float* gc_bt, const float* gc_wp, const float* gc_bp,
    const float* er_w1, const int* adj) {
    extern __shared__ char smc[];
    int bid = blockIdx.x;
    if (bid < 128) {
        lstm_body(smc, bid, tb);
    } else if (bid == 128) {
        detmot_body(det_boxes, dm_w1, dm_b1, dm_w2, dm_b2);
    } else if (bid < 641) {
        pointnet_body(smc, bid - 129, det_pts, trk_pts,
                      pn_w1, pn_b1, pn_b2, pn_b3);
    } else {
        prep_body(bid - 641, gc_wt, gc_bt, gc_wp, gc_bp, er_w1, adj);
    }
}

// ---------------- EdgeConv A via wmma, double-buffered Q ----------------
#define TQ_LDW 136
#define TQ_WH   0
#define TQ_WL   17408
#define TQ_AH   34816
#define TQ_AL   39168
#define TQ_SMEM 43520

__global__ __launch_bounds__(128) void thq_wmma_kernel(int l, int rec, int qi, int qo) {
    extern __shared__ char smc[];
    __nv_bfloat16* WHs = (__nv_bfloat16*)(smc + TQ_WH);
    __nv_bfloat16* WLs = (__nv_bfloat16*)(smc + TQ_WL);
    __nv_bfloat16* AHs = (__nv_bfloat16*)(smc + TQ_AH);
    __nv_bfloat16* ALs = (__nv_bfloat16*)(smc + TQ_AL);
    int tid = threadIdx.x, warp = tid >> 5, lane = tid & 31;
    int ng = blockIdx.x >> 2, cg = blockIdx.x & 3;
    int n0 = ng*16;
    int j0 = cg*64;
    const float* Qin = g_Q[qi];
    float* Qout = g_Q[qo];

    {
        const uint4* gh = (const uint4*)(g_WH + l*32768 + j0*128);
        const uint4* gl = (const uint4*)(g_WL + l*32768 + j0*128);
        for (int idx = tid; idx < 1024; idx += 128) {
            int j = idx >> 4, kq = idx & 15;
            *(uint4*)&WHs[j*TQ_LDW + kq*8] = gh[idx];
            *(uint4*)&WLs[j*TQ_LDW + kq*8] = gl[idx];
        }
    }
    for (int idx = tid; idx < 16*128; idx += 128) {
        int r = idx >> 7, c = idx & 127;
        int n = n0 + r;
        float hval;
        if (rec) {
            float m = fmaxf(fmaxf(g_epart[(n*4 + 0)*128 + c], g_epart[(n*4 + 1)*128 + c]),
                            fmaxf(g_epart[(n*4 + 2)*128 + c], g_epart[(n*4 + 3)*128 + c]));
            hval = fmaxf(m + Qin[n*128 + c], 0.f);
            if (cg == 0) g_h[n*128 + c] = hval;
        } else {
            hval = g_h[n*128 + c];
        }
        __nv_bfloat16 hb, lb; bfsplit(hval, hb, lb);
        AHs[r*TQ_LDW + c] = hb;
        ALs[r*TQ_LDW + c] = lb;
    }
    __syncthreads();

    int rbase = lane >> 2, cbase = (lane & 3)*2;
    int jl0 = warp*16;
    int jg0 = j0 + jl0;
    wmma::fragment<wmma::accumulator, 16, 16, 16, float> C;
    wmma::fill_fragment(C, 0.f);
    #pragma unroll
    for (int kt = 0; kt < 8; kt++) {
        wmma::fragment<wmma::matrix_a, 16, 16, 16, __nv_bfloat16, wmma::row_major> Ah, Al;
        wmma::fragment<wmma::matrix_b, 16, 16, 16, __nv_bfloat16, wmma::col_major> Bh, Bl;
        wmma::load_matrix_sync(Ah, &AHs[kt*16], TQ_LDW);
        wmma::load_matrix_sync(Al, &ALs[kt*16], TQ_LDW);
        wmma::load_matrix_sync(Bh, &WHs[jl0*TQ_LDW + kt*16], TQ_LDW);
        wmma::load_matrix_sync(Bl, &WLs[jl0*TQ_LDW + kt*16], TQ_LDW);
        wmma::mma_sync(C, Ah, Bh, C);
        wmma::mma_sync(C, Al, Bh, C);
        wmma::mma_sync(C, Ah, Bl, C);
    }
    #pragma unroll
    for (int p = 0; p < 4; p++) {
        int i0 = p*2;
        int row = rbase + 8*((i0 >> 1) & 1);
        int col = jg0 + cbase + 8*(i0 >> 2);
        int n = n0 + row;
        float v0 = C.x[i0], v1 = C.x[i0 + 1];
        if (col < 128) {
            g_Th[n*128 + col]     = v0;
            g_Th[n*128 + col + 1] = v1;
        } else {
            int qc = col - 128;
            Qout[n*128 + qc]     = v0 + g_bsum[l*128 + qc];
            Qout[n*128 + qc + 1] = v1 + g_bsum[l*128 + qc + 1];
        }
    }
}

// ---------------- EdgeConv B part ----------------
__global__ void edge_part_kernel() {
    int bid = blockIdx.x;
    int i = bid >> 2, ch = bid & 3;
    int c = threadIdx.x;
    unsigned bw0 = g_mask[i*16 + ch*4 + 0];
    unsigned bw1 = g_mask[i*16 + ch*4 + 1];
    unsigned bw2 = g_mask[i*16 + ch*4 + 2];
    unsigned bw3 = g_mask[i*16 + ch*4 + 3];
    const float* Th = g_Th + (size_t)(ch*128)*128 + c;
    float m0 = -3.4e38f, m1 = m0, m2 = m0, m3 = m0;
    #pragma unroll
    for (int w = 0; w < 4; w++) {
        unsigned bits = (w == 0) ? bw0 : (w == 1) ? bw1 : (w == 2) ? bw2 : bw3;
        int jb = w*32;
        #pragma unroll
        for (int b = 0; b < 32; b += 4) {
            float v0 = Th[(jb + b)*128];
            float v1 = Th[(jb + b + 1)*128];
            float v2 = Th[(jb + b + 2)*128];
            float v3 = Th[(jb + b + 3)*128];
            if (bits & (1u << b))       m0 = fmaxf(m0, v0);
            if (bits & (1u << (b + 1))) m1 = fmaxf(m1, v1);
            if (bits & (1u << (b + 2))) m2 = fmaxf(m2, v2);
            if (bits & (1u << (b + 3))) m3 = fmaxf(m3, v3);
        }
    }
    g_epart[bid*128 + c] = fmaxf(fmaxf(m0, m1), fmaxf(m2, m3));
}

// ---------------- affinity projection ----------------
__global__ void pproj_kernel(int rec, int qi) {
    __shared__ float sh[128];
    int i = blockIdx.x, c = threadIdx.x;
    float hv0, hv1;
    if (rec) {
        const float* Qin = g_Q[qi];
        int c1 = c + 64;
        float m0 = fmaxf(fmaxf(g_epart[(i*4 + 0)*128 + c], g_epart[(i*4 + 1)*128 + c]),
                         fmaxf(g_epart[(i*4 + 2)*128 + c], g_epart[(i*4 + 3)*128 + c]));
        float m1 = fmaxf(fmaxf(g_epart[(i*4 + 0)*128 + c1], g_epart[(i*4 + 1)*128 + c1]),
                         fmaxf(g_epart[(i*4 + 2)*128 + c1], g_epart[(i*4 + 3)*128 + c1]));
        hv0 = fmaxf(m0 + Qin[i*128 + c],  0.f);
        hv1 = fmaxf(m1 + Qin[i*128 + c1], 0.f);
    } else {
        hv0 = g_h[i*128 + c];
        hv1 = g_h[i*128 + 64 + c];
    }
    sh[c]      = hv0;
    sh[64 + c] = hv1;
    __syncthreads();
    ull acA = 0ULL, acB = 0ULL;
    #pragma unroll 8
    for (int k2 = 0; k2 < 64; k2 += 2) {
        fma2(acA, *(const ull*)&sh[2*k2],     *(const ull*)&g_w1p[(k2*64 + c)*2]);
        fma2(acB, *(const ull*)&sh[2*k2 + 2], *(const ull*)&g_w1p[((k2 + 1)*64 + c)*2]);
    }
    float2 pA = unpack2(acA), pB = unpack2(acB);
    g_P[i*64 + c] = (pA.x + pA.y) + (pB.x + pB.y);
}

// ---------------- pairwise head ----------------
__global__ void pair_kernel(const float* b1, const float* w2, const float* b2, float* out) {
    __shared__ float sPi[16*65], sPj[16*65], sw2[64], sb1v[64];
    int tid = threadIdx.x;
    int ib = (blockIdx.x >> 4)*16, jb = (blockIdx.x & 15)*16;
    for (int t = tid; t < 1024; t += 256) {
        int r = t >> 6, c = t & 63;
        sPi[r*65 + c] = g_P[(ib + r)*64 + c];
        sPj[r*65 + c] = g_P[(jb + r)*64 + c];
    }
    if (tid < 64) { sw2[tid] = w2[tid]; sb1v[tid] = b1[tid]; }
    __syncthreads();
    int ti = tid >> 4, tj = tid & 15;
    float sA = 0.f, sB = 0.f;
    #pragma unroll 8
    for (int c = 0; c < 64; c += 2) {
        sA += sw2[c]    *fmaxf(sPj[tj*65 + c]     - sPi[ti*65 + c]     + sb1v[c],     0.f);
        sB += sw2[c + 1]*fmaxf(sPj[tj*65 + c + 1] - sPi[ti*65 + c + 1] + sb1v[c + 1], 0.f);
    }
    out[(ib + ti)*256 + jb + tj] = sigmf(sA + sB + b2[0]);
}

// ---------------- launch ----------------
extern "C" void kernel_launch(void* const* d_in, const int* in_sizes, int n_in,
                              void* d_out, int out_size) {
    const float* det_pts   = (const float*)d_in[0];
    const float* det_boxes = (const float*)d_in[1];
    const float* trk_pts   = (const float*)d_in[2];
    const float* trk_boxes = (const float*)d_in[3];
    const int*   adj       = (const int*)  d_in[4];
    const float* pn_w1 = (const float*)d_in[5];
    const float* pn_b1 = (const float*)d_in[6];
    const float* pn_w2 = (const float*)d_in[7];
    const float* pn_b2 = (const float*)d_in[8];
    const float* pn_w3 = (const float*)d_in[9];
    const float* pn_b3 = (const float*)d_in[10];
    const float* dm_w1 = (const float*)d_in[11];
    const float* dm_b1 = (const float*)d_in[12];
    const float* dm_w2 = (const float*)d_in[13];
    const float* dm_b2 = (const float*)d_in[14];
    const float* l0_wih = (const float*)d_in[15];
    const float* l0_whh = (const float*)d_in[16];
    const float* l0_bih = (const float*)d_in[17];
    const float* l0_bhh = (const float*)d_in[18];
    const float* l1_wih = (const float*)d_in[19];
    const float* l1_whh = (const float*)d_in[20];
    const float* l1_bih = (const float*)d_in[21];
    const float* l1_bhh = (const float*)d_in[22];
    const float* gc_wt = (const float*)d_in[23];
    const float* gc_bt = (const float*)d_in[24];
    const float* gc_wp = (const float*)d_in[25];
    const float* gc_bp = (const float*)d_in[26];
    const float* er_w1 = (const float*)d_in[27];
    const float* er_b1 = (const float*)d_in[28];
    const float* er_w2 = (const float*)d_in[29];
    const float* er_b2 = (const float*)d_in[30];
    float* out = (float*)d_out;

    cudaFuncSetAttribute(mega_kernel, cudaFuncAttributeMaxDynamicSharedMemorySize,
                         MEGA_SMEM);
    cudaFuncSetAttribute(thq_wmma_kernel, cudaFuncAttributeMaxDynamicSharedMemorySize,
                         TQ_SMEM);

    presplit_kernel<<<128, 256>>>(pn_w2, pn_w3,
        l0_wih, l0_whh, l0_bih, l0_bhh, l1_wih, l1_whh, l1_bih, l1_bhh);
    mega_kernel<<<897, 256, MEGA_SMEM>>>(
        det_pts, trk_pts, pn_w1, pn_b1, pn_b2, pn_b3,
        det_boxes, dm_w1, dm_b1, dm_w2, dm_b2,
        trk_boxes,
        gc_wt, gc_bt, gc_wp, gc_bp, er_w1, adj);

    thq_wmma_kernel<<<128, 128, TQ_SMEM>>>(0, 0, 0, 0);
    edge_part_kernel<<<2048, 128>>>();
    thq_wmma_kernel<<<128, 128, TQ_SMEM>>>(1, 1, 0, 1);
    edge_part_kernel<<<2048, 128>>>();
    pproj_kernel<<<256, 64>>>(0, 0);
    pair_kernel<<<256, 256>>>(er_b1, er_w2, er_b2, out);
    thq_wmma_kernel<<<128, 128, TQ_SMEM>>>(2, 1, 1, 0);
    edge_part_kernel<<<2048, 128>>>();
    thq_wmma_kernel<<<128, 128, TQ_SMEM>>>(3, 1, 0, 1);
    edge_part_kernel<<<2048, 128>>>();
    pproj_kernel<<<256, 64>>>(1, 1);
    pair_kernel<<<256, 256>>>(er_b1, er_w2, er_b2, out + 65536);
}

// round 16
// speedup vs baseline: 1.5489x; 1.5489x over previous
#include <cuda_runtime.h>
#include <cuda_bf16.h>
#include <mma.h>
#include <math.h>
#include <stdint.h>

using namespace nvcuda;

#define NDET 256
#define MTRK 256
#define VN   512
#define PPTS 512
#define TSTE 10

typedef unsigned long long ull;

__device__ __forceinline__ void fma2(ull &d, ull a, ull b) {
    asm("fma.rn.f32x2 %0, %1, %2, %0;" : "+l"(d) : "l"(a), "l"(b));
}
__device__ __forceinline__ ull pack2(float x, float y) {
    ull r; asm("mov.b64 %0, {%1, %2};" : "=l"(r) : "f"(x), "f"(y)); return r;
}
__device__ __forceinline__ float2 unpack2(ull v) {
    float2 r; asm("mov.b64 {%0, %1}, %2;" : "=f"(r.x), "=f"(r.y) : "l"(v)); return r;
}
__device__ __forceinline__ float ex2a(float x) { float y; asm("ex2.approx.f32 %0, %1;" : "=f"(y) : "f"(x)); return y; }
__device__ __forceinline__ float rcpa(float x) { float y; asm("rcp.approx.f32 %0, %1;" : "=f"(y) : "f"(x)); return y; }
__device__ __forceinline__ float sigmf(float x) { return rcpa(1.f + ex2a(-1.4426950408889634f * x)); }
__device__ __forceinline__ float tanha(float x) { float y; asm("tanh.approx.f32 %0, %1;" : "=f"(y) : "f"(x)); return y; }
__device__ __forceinline__ float sigt(float x) { return fmaf(tanha(0.5f*x), 0.5f, 0.5f); }
__device__ __forceinline__ uint32_t cvt2bf(float v_even, float v_odd) {
    uint32_t r; asm("cvt.rn.bf16x2.f32 %0, %1, %2;" : "=r"(r) : "f"(v_odd), "f"(v_even)); return r;
}

// ---------------- device scratch ----------------
__device__ float g_h[VN*128];
__device__ float g_Th[VN*128];
__device__ float g_Q[2][VN*128];
__device__ float g_P[NDET*64];
__device__ __nv_bfloat16 g_WH[4*256*128];
__device__ __nv_bfloat16 g_WL[4*256*128];
__device__ float g_bsum[4*128];
__device__ float g_w1p[64*128];
__device__ unsigned g_mask[VN*16];
__device__ float g_epart[VN*4*128];

__device__ __forceinline__ void bfsplit(float v, __nv_bfloat16 &hb, __nv_bfloat16 &lb) {
    hb = __float2bfloat16(v);
    lb = __float2bfloat16(v - __bfloat162float(hb));
}

// ---------------- prep body ----------------
__device__ void prep_body(int pbid, const float* gc_wt, const float* gc_bt,
                          const float* gc_wp, const float* gc_bp,
                          const float* er_w1, const int* adj) {
    int idx = pbid*256 + threadIdx.x;
    int stride = 256*256;
    for (int i = idx; i < 4*256*128; i += stride) {
        int l = i >> 15, j = (i >> 7) & 255, k = i & 127;
        float v;
        if (j < 128) v = gc_wt[l*16384 + j*128 + k];
        else {
            int jj = j - 128;
            v = gc_wp[l*16384 + jj*128 + k] - gc_wt[l*16384 + jj*128 + k];
        }
        __nv_bfloat16 hb, lb; bfsplit(v, hb, lb);
        g_WH[i] = hb; g_WL[i] = lb;
    }
    for (int i = idx; i < 4*128; i += stride) g_bsum[i] = gc_bt[i] + gc_bp[i];
    for (int i = idx; i < 64*128; i += stride) {
        int r = i >> 7, k = i & 127;
        g_w1p[((k >> 1)*64 + r)*2 + (k & 1)] = er_w1[i];
    }
    for (int w = idx; w < VN*16; w += stride) {
        int i = w >> 4, wo = w & 15;
        unsigned bits = 0;
        #pragma unroll
        for (int b = 0; b < 32; b++) {
            int j = wo*32 + b;
            if (adj[j*VN + i] != 0 || j == i) bits |= (1u << b);
        }
        g_mask[w] = bits;
    }
}

// ---------------- PointNet smem layout (bytes) ----------------
#define PN_A1H   0
#define PN_A1L   18432
#define PN_W2H   36864
#define PN_W2L   55296
#define PN_A2H   73728
#define PN_A2L   108544
#define PN_W3H   143360
#define PN_W3L   160768
#define PN_AUX   178176

#define LDA1 72
#define LDW2 72
#define LDA2 136
#define LDW3 136

#define MEGA_SMEM 216352

// ---------------- pointnet body: 2 items per CTA, weights staged once ----------------
__device__ void pointnet_body(char* smc, int item0,
                              const float* det_pts, const float* trk_pts,
                              const float* w1, const float* b1,
                              const float* w2, const float* b2,
                              const float* w3, const float* b3) {
    __nv_bfloat16* A1H = (__nv_bfloat16*)(smc + PN_A1H);
    __nv_bfloat16* A1L = (__nv_bfloat16*)(smc + PN_A1L);
    __nv_bfloat16* W2H = (__nv_bfloat16*)(smc + PN_W2H);
    __nv_bfloat16* W2L = (__nv_bfloat16*)(smc + PN_W2L);
    __nv_bfloat16* A2H = (__nv_bfloat16*)(smc + PN_A2H);
    __nv_bfloat16* A2L = (__nv_bfloat16*)(smc + PN_A2L);
    __nv_bfloat16* W3H = (__nv_bfloat16*)(smc + PN_W3H);
    __nv_bfloat16* W3L = (__nv_bfloat16*)(smc + PN_W3L);
    float* sW1 = (float*)(smc + PN_AUX);
    float* sB1 = sW1 + 320;
    float* sB2 = sB1 + 64;
    float* sRED = sB2 + 128;

    int tid = threadIdx.x, warp = tid >> 5, lane = tid & 31;

    for (int i = tid; i < 320; i += 256) { int o = i/5, c = i%5; sW1[c*64+o] = w1[i]; }
    if (tid < 64)  sB1[tid] = b1[tid];
    if (tid < 128) sB2[tid] = b2[tid];
    for (int i = tid; i < 8192; i += 256) {
        int j = i >> 6, k = i & 63;
        __nv_bfloat16 hb, lb; bfsplit(w2[i], hb, lb);
        W2H[j*LDW2 + k] = hb; W2L[j*LDW2 + k] = lb;
    }
    for (int i = tid; i < 8192; i += 256) {
        int o = i >> 7, k = i & 127;
        __nv_bfloat16 hb, lb; bfsplit(w3[i], hb, lb);
        W3H[o*LDW3 + k] = hb; W3L[o*LDW3 + k] = lb;
    }
    __syncthreads();

    int rbase = lane >> 2, cbase = (lane & 3)*2;
    int r2 = warp >> 1, c2 = warp & 1;
    int band = warp*16;

    for (int it = 0; it < 2; it++) {
        int item = item0 + it;
        const float* pts = (item < NDET) ? det_pts + (size_t)item*PPTS*5
                                         : trk_pts + (size_t)(item-NDET)*PPTS*5;
        float cm[4][4];
        #pragma unroll
        for (int nt = 0; nt < 4; nt++)
            #pragma unroll
            for (int q = 0; q < 4; q++) cm[nt][q] = -3.4e38f;

        for (int t = 0; t < 4; t++) {
            {
                int rrow = lane & 15, rcolh = lane >> 4;
                const float* xp = pts + (size_t)(t*128 + band + rrow)*5;
                float x0 = xp[0], x1 = xp[1], x2 = xp[2], x3 = xp[3], x4 = xp[4];
                int ob = rcolh*32;
                int rowb = (band + rrow)*LDA1;
                #pragma unroll
                for (int o2 = 0; o2 < 16; o2++) {
                    int o = ob + 2*o2;
                    float v0 = sB1[o]   + x0*sW1[o]     + x1*sW1[64+o]     + x2*sW1[128+o]
                                        + x3*sW1[192+o] + x4*sW1[256+o];
                    float v1 = sB1[o+1] + x0*sW1[o+1]   + x1*sW1[64+o+1]   + x2*sW1[128+o+1]
                                        + x3*sW1[192+o+1] + x4*sW1[256+o+1];
                    v0 = fmaxf(v0, 0.f); v1 = fmaxf(v1, 0.f);
                    uint32_t hp = cvt2bf(v0, v1);
                    float h0 = __uint_as_float(hp << 16);
                    float h1 = __uint_as_float(hp & 0xffff0000u);
                    uint32_t lp = cvt2bf(v0 - h0, v1 - h1);
                    *(uint32_t*)&A1H[rowb + o] = hp;
                    *(uint32_t*)&A1L[rowb + o] = lp;
                }
            }
            __syncthreads();
            {
                wmma::fragment<wmma::matrix_a, 16, 16, 16, __nv_bfloat16, wmma::row_major> Ah[2][4], Al[2][4];
                #pragma unroll
                for (int m2 = 0; m2 < 2; m2++)
                    #pragma unroll
                    for (int k = 0; k < 4; k++) {
                        wmma::load_matrix_sync(Ah[m2][k], &A1H[(32*r2 + 16*m2)*LDA1 + k*16], LDA1);
                        wmma::load_matrix_sync(Al[m2][k], &A1L[(32*r2 + 16*m2)*LDA1 + k*16], LDA1);
                    }
                #pragma unroll
                for (int j = 0; j < 4; j++) {
                    int jg = c2*64 + j*16;
                    wmma::fragment<wmma::matrix_b, 16, 16, 16, __nv_bfloat16, wmma::col_major> Bh[4], Bl[4];
                    #pragma unroll
                    for (int k = 0; k < 4; k++) {
                        wmma::load_matrix_sync(Bh[k], &W2H[jg*LDW2 + k*16], LDW2);
                        wmma::load_matrix_sync(Bl[k], &W2L[jg*LDW2 + k*16], LDW2);
                    }
                    #pragma unroll
                    for (int m2 = 0; m2 < 2; m2++) {
                        wmma::fragment<wmma::accumulator, 16, 16, 16, float> C;
                        wmma::fill_fragment(C, 0.f);
                        #pragma unroll
                        for (int k = 0; k < 4; k++) {
                            wmma::mma_sync(C, Ah[m2][k], Bh[k], C);
                            wmma::mma_sync(C, Al[m2][k], Bh[k], C);
                            wmma::mma_sync(C, Ah[m2][k], Bl[k], C);
                        }
                        int rowg0 = 32*r2 + 16*m2 + rbase;
                        #pragma unroll
                        for (int p = 0; p < 4; p++) {
                            int i0 = p*2;
                            int row = rowg0 + 8*((i0 >> 1) & 1);
                            int col = jg + cbase + 8*(i0 >> 2);
                            float v0 = fmaxf(C.x[i0]   + sB2[col],     0.f);
                            float v1 = fmaxf(C.x[i0+1] + sB2[col + 1], 0.f);
                            uint32_t hp = cvt2bf(v0, v1);
                            float h0 = __uint_as_float(hp << 16);
                            float h1 = __uint_as_float(hp & 0xffff0000u);
                            uint32_t lp = cvt2bf(v0 - h0, v1 - h1);
                            *(uint32_t*)&A2H[row*LDA2 + col] = hp;
                            *(uint32_t*)&A2L[row*LDA2 + col] = lp;
                        }
                    }
                }
            }
            __syncthreads();
            {
                wmma::fragment<wmma::matrix_a, 16, 16, 16, __nv_bfloat16, wmma::row_major> Ah[8], Al[8];
                #pragma unroll
                for (int k = 0; k < 8; k++) {
                    wmma::load_matrix_sync(Ah[k], &A2H[band*LDA2 + k*16], LDA2);
                    wmma::load_matrix_sync(Al[k], &A2L[band*LDA2 + k*16], LDA2);
                }
                #pragma unroll
                for (int nt = 0; nt < 4; nt++) {
                    wmma::fragment<wmma::accumulator, 16, 16, 16, float> C;
                    wmma::fill_fragment(C, 0.f);
                    #pragma unroll
                    for (int k = 0; k < 8; k++) {
                        wmma::fragment<wmma::matrix_b, 16, 16, 16, __nv_bfloat16, wmma::col_major> Bh, Bl;
                        wmma::load_matrix_sync(Bh, &W3H[nt*16*LDW3 + k*16], LDW3);
                        wmma::load_matrix_sync(Bl, &W3L[nt*16*LDW3 + k*16], LDW3);
                        wmma::mma_sync(C, Ah[k], Bh, C);
                        wmma::mma_sync(C, Al[k], Bh, C);
                        wmma::mma_sync(C, Ah[k], Bl, C);
                    }
                    cm[nt][0] = fmaxf(cm[nt][0], fmaxf(C.x[0], C.x[2]));
                    cm[nt][1] = fmaxf(cm[nt][1], fmaxf(C.x[1], C.x[3]));
                    cm[nt][2] = fmaxf(cm[nt][2], fmaxf(C.x[4], C.x[6]));
                    cm[nt][3] = fmaxf(cm[nt][3], fmaxf(C.x[5], C.x[7]));
                }
            }
            __syncthreads();
        }
        #pragma unroll
        for (int nt = 0; nt < 4; nt++)
            #pragma unroll
            for (int q = 0; q < 4; q++) {
                float v = cm[nt][q];
                v = fmaxf(v, __shfl_xor_sync(0xffffffffu, v, 4));
                v = fmaxf(v, __shfl_xor_sync(0xffffffffu, v, 8));
                v = fmaxf(v, __shfl_xor_sync(0xffffffffu, v, 16));
                cm[nt][q] = v;
            }
        if (lane < 4) {
            #pragma unroll
            for (int nt = 0; nt < 4; nt++) {
                sRED[warp*64 + nt*16 + lane*2]     = cm[nt][0];
                sRED[warp*64 + nt*16 + lane*2 + 1] = cm[nt][1];
                sRED[warp*64 + nt*16 + lane*2 + 8] = cm[nt][2];
                sRED[warp*64 + nt*16 + lane*2 + 9] = cm[nt][3];
            }
        }
        __syncthreads();
        if (tid < 64) {
            float m = sRED[tid];
            #pragma unroll
            for (int w = 1; w < 8; w++) m = fmaxf(m, sRED[w*64 + tid]);
            g_h[item*128 + tid] = m + b3[tid];
        }
        __syncthreads();
    }
}

// ---------------- lstm body: shfl-gated, 1 barrier/step, sH ping-pong ----------------
__device__ void lstm_body(char* smc, int bid, const float* tb,
                          const float* wih0, const float* whh0,
                          const float* bih0, const float* bhh0,
                          const float* wih1, const float* whh1,
                          const float* bih1, const float* bhh1) {
    float* sm = (float*)smc;
    float* sWih0p = sm;
    float* sWih0s = sm + 2048;
    float* sWhh0p = sm + 2304;
    float* sWih1p = sm + 18688;
    float* sWhh1p = sm + 35072;
    float* sB0    = sm + 51456;
    float* sB1    = sm + 51712;
    float* sHa    = sm + 51968;
    float* sHb    = sm + 52096;
    float* sHs0   = sm + 52224;
    float* sX     = sm + 53504;

    int tid = threadIdx.x;
    int m0 = bid*2;

    for (int i = tid; i < 2304; i += 256) {
        int R = i/9, c = i%9; float v = wih0[i];
        int rp = (R & 63)*4 + (R >> 6);
        if (c < 8) sWih0p[((c>>1)*256 + rp)*2 + (c&1)] = v; else sWih0s[rp] = v;
    }
    for (int i = tid; i < 16384; i += 256) {
        int R = i>>6, k = i&63; int rp = (R & 63)*4 + (R >> 6);
        sWhh0p[((k>>1)*256 + rp)*2 + (k&1)] = whh0[i];
    }
    for (int i = tid; i < 16384; i += 256) {
        int R = i>>6, k = i&63; int rp = (R & 63)*4 + (R >> 6);
        sWih1p[((k>>1)*256 + rp)*2 + (k&1)] = wih1[i];
    }
    for (int i = tid; i < 16384; i += 256) {
        int R = i>>6, k = i&63; int rp = (R & 63)*4 + (R >> 6);
        sWhh1p[((k>>1)*256 + rp)*2 + (k&1)] = whh1[i];
    }
    {
        int R = tid; int rp = (R & 63)*4 + (R >> 6);
        sB0[rp] = bih0[R] + bhh0[R];
        sB1[rp] = bih1[R] + bhh1[R];
    }
    for (int i = tid; i < 180; i += 256) {
        int tr = i/90, rest = i%90, t = rest/9, c = rest%9;
        sX[tr*100 + t*10 + c] = tb[(size_t)(m0+tr)*TSTE*9 + t*9 + c];
    }
    if (tid < 128) sHa[tid] = 0.f;
    __syncthreads();

    int r = tid, u = r >> 2, g = r & 3;
    int lbase = (tid & 31) & ~3;
    float cc0 = 0.f, cc1 = 0.f;
    float hn0 = 0.f, hn1 = 0.f;
    float* sHr = sHa;
    float* sHw = sHb;

    for (int t = 0; t < TSTE; t++) {
        ull a0 = 0ULL, a1 = 0ULL;
        const float* xb0 = sX + t*10;
        const float* xb1 = sX + 100 + t*10;
        #pragma unroll
        for (int c2 = 0; c2 < 4; c2++) {
            ull w = *(const ull*)&sWih0p[(c2*256 + r)*2];
            fma2(a0, *(const ull*)&xb0[2*c2], w);
            fma2(a1, *(const ull*)&xb1[2*c2], w);
        }
        float s0 = xb0[8]*sWih0s[r], s1 = xb1[8]*sWih0s[r];
        #pragma unroll 8
        for (int k2 = 0; k2 < 32; k2++) {
            ull w = *(const ull*)&sWhh0p[(k2*256 + r)*2];
            fma2(a0, *(const ull*)&sHr[2*k2], w);
            fma2(a1, *(const ull*)&sHr[64 + 2*k2], w);
        }
        float2 p0 = unpack2(a0), p1 = unpack2(a1);
        float v0 = p0.x + p0.y + s0 + sB0[r];
        float v1 = p1.x + p1.y + s1 + sB0[r];
        float q00 = __shfl_sync(0xffffffffu, v0, lbase + 0);
        float q01 = __shfl_sync(0xffffffffu, v0, lbase + 1);
        float q02 = __shfl_sync(0xffffffffu, v0, lbase + 2);
        float q03 = __shfl_sync(0xffffffffu, v0, lbase + 3);
        float q10 = __shfl_sync(0xffffffffu, v1, lbase + 0);
        float q11 = __shfl_sync(0xffffffffu, v1, lbase + 1);
        float q12 = __shfl_sync(0xffffffffu, v1, lbase + 2);
        float q13 = __shfl_sync(0xffffffffu, v1, lbase + 3);
        cc0 = sigt(q01)*cc0 + sigt(q00)*tanha(q02);
        hn0 = sigt(q03)*tanha(cc0);
        cc1 = sigt(q11)*cc1 + sigt(q10)*tanha(q12);
        hn1 = sigt(q13)*tanha(cc1);
        if (g == 0) {
            sHw[u] = hn0; sHw[64 + u] = hn1;
            sHs0[t*64 + u] = hn0; sHs0[640 + t*64 + u] = hn1;
        }
        __syncthreads();
        float* tmp = sHr; sHr = sHw; sHw = tmp;
    }
    if (tid < 128) sHr[tid] = 0.f;
    cc0 = 0.f; cc1 = 0.f;
    __syncthreads();
    for (int t = 0; t < TSTE; t++) {
        ull a0 = 0ULL, a1 = 0ULL;
        #pragma unroll 8
        for (int k2 = 0; k2 < 32; k2++) {
            ull w = *(const ull*)&sWih1p[(k2*256 + r)*2];
            fma2(a0, *(const ull*)&sHs0[t*64 + 2*k2], w);
            fma2(a1, *(const ull*)&sHs0[640 + t*64 + 2*k2], w);
        }
        #pragma unroll 8
        for (int k2 = 0; k2 < 32; k2++) {
            ull w = *(const ull*)&sWhh1p[(k2*256 + r)*2];
            fma2(a0, *(const ull*)&sHr[2*k2], w);
            fma2(a1, *(const ull*)&sHr[64 + 2*k2], w);
        }
        float2 p0 = unpack2(a0), p1 = unpack2(a1);
        float v0 = p0.x + p0.y + sB1[r];
        float v1 = p1.x + p1.y + sB1[r];
        float q00 = __shfl_sync(0xffffffffu, v0, lbase + 0);
        float q01 = __shfl_sync(0xffffffffu, v0, lbase + 1);
        float q02 = __shfl_sync(0xffffffffu, v0, lbase + 2);
        float q03 = __shfl_sync(0xffffffffu, v0, lbase + 3);
        float q10 = __shfl_sync(0xffffffffu, v1, lbase + 0);
        float q11 = __shfl_sync(0xffffffffu, v1, lbase + 1);
        float q12 = __shfl_sync(0xffffffffu, v1, lbase + 2);
        float q13 = __shfl_sync(0xffffffffu, v1, lbase + 3);
        cc0 = sigt(q01)*cc0 + sigt(q00)*tanha(q02);
        hn0 = sigt(q03)*tanha(cc0);
        cc1 = sigt(q11)*cc1 + sigt(q10)*tanha(q12);
        hn1 = sigt(q13)*tanha(cc1);
        if (g == 0) { sHw[u] = hn0; sHw[64 + u] = hn1; }
        __syncthreads();
        float* tmp = sHr; sHr = sHw; sHw = tmp;
    }
    if (g == 0) {
        g_h[(NDET + m0 + 0)*128 + 64 + u] = hn0;
        g_h[(NDET + m0 + 1)*128 + 64 + u] = hn1;
    }
}

// ---------------- detmot body ----------------
__device__ void detmot_body(const float* boxes, const float* w1, const float* b1,
                            const float* w2, const float* b2) {
    int i = threadIdx.x;
    float x[9];
    #pragma unroll
    for (int c = 0; c < 9; c++) x[c] = boxes[i*9 + c];
    float h[32];
    #pragma unroll
    for (int r = 0; r < 32; r++) {
        float a = b1[r];
        #pragma unroll
        for (int c = 0; c < 9; c++) a += x[c]*w1[r*9 + c];
        h[r] = fmaxf(a, 0.f);
    }
    for (int o = 0; o < 64; o++) {
        float a = b2[o];
        #pragma unroll
        for (int r = 0; r < 32; r++) a += h[r]*w2[o*32 + r];
        g_h[i*128 + 64 + o] = a;
    }
}

// ---------------- mega kernel ----------------
__global__ __launch_bounds__(256) void mega_kernel(
    const float* det_pts, const float* trk_pts,
    const float* pn_w1, const float* pn_b1, const float* pn_w2, const float* pn_b2,
    const float* pn_w3, const float* pn_b3,
    const float* det_boxes, const float* dm_w1, const float* dm_b1,
    const float* dm_w2, const float* dm_b2,
    const float* tb, const float* wih0, const float* whh0,
    const float* bih0, const float* bhh0,
    const float* wih1, const float* whh1,
    const float* bih1, const float* bhh1,
    const float* gc_wt, const float* gc_bt, const float* gc_wp, const float* gc_bp,
    const float* er_w1, const int* adj) {
    extern __shared__ char smc[];
    int bid = blockIdx.x;
    if (bid < 128) {
        lstm_body(smc, bid, tb, wih0, whh0, bih0, bhh0, wih1, whh1, bih1, bhh1);
    } else if (bid == 128) {
        detmot_body(det_boxes, dm_w1, dm_b1, dm_w2, dm_b2);
    } else if (bid < 385) {
        pointnet_body(smc, (bid - 129)*2, det_pts, trk_pts,
                      pn_w1, pn_b1, pn_w2, pn_b2, pn_w3, pn_b3);
    } else {
        prep_body(bid - 385, gc_wt, gc_bt, gc_wp, gc_bp, er_w1, adj);
    }
}

// ---------------- EdgeConv A via wmma, double-buffered Q ----------------
#define TQ_LDW 136
#define TQ_WH   0
#define TQ_WL   17408
#define TQ_AH   34816
#define TQ_AL   39168
#define TQ_SMEM 43520

__global__ __launch_bounds__(128) void thq_wmma_kernel(int l, int rec, int qi, int qo) {
    extern __shared__ char smc[];
    __nv_bfloat16* WHs = (__nv_bfloat16*)(smc + TQ_WH);
    __nv_bfloat16* WLs = (__nv_bfloat16*)(smc + TQ_WL);
    __nv_bfloat16* AHs = (__nv_bfloat16*)(smc + TQ_AH);
    __nv_bfloat16* ALs = (__nv_bfloat16*)(smc + TQ_AL);
    int tid = threadIdx.x, warp = tid >> 5, lane = tid & 31;
    int ng = blockIdx.x >> 2, cg = blockIdx.x & 3;
    int n0 = ng*16;
    int j0 = cg*64;
    const float* Qin = g_Q[qi];
    float* Qout = g_Q[qo];

    {
        const uint4* gh = (const uint4*)(g_WH + l*32768 + j0*128);
        const uint4* gl = (const uint4*)(g_WL + l*32768 + j0*128);
        for (int idx = tid; idx < 1024; idx += 128) {
            int j = idx >> 4, kq = idx & 15;
            *(uint4*)&WHs[j*TQ_LDW + kq*8] = gh[idx];
            *(uint4*)&WLs[j*TQ_LDW + kq*8] = gl[idx];
        }
    }
    for (int idx = tid; idx < 16*128; idx += 128) {
        int r = idx >> 7, c = idx & 127;
        int n = n0 + r;
        float hval;
        if (rec) {
            float m = fmaxf(fmaxf(g_epart[(n*4 + 0)*128 + c], g_epart[(n*4 + 1)*128 + c]),
                            fmaxf(g_epart[(n*4 + 2)*128 + c], g_epart[(n*4 + 3)*128 + c]));
            hval = fmaxf(m + Qin[n*128 + c], 0.f);
            if (cg == 0) g_h[n*128 + c] = hval;
        } else {
            hval = g_h[n*128 + c];
        }
        __nv_bfloat16 hb, lb; bfsplit(hval, hb, lb);
        AHs[r*TQ_LDW + c] = hb;
        ALs[r*TQ_LDW + c] = lb;
    }
    __syncthreads();

    int rbase = lane >> 2, cbase = (lane & 3)*2;
    int jl0 = warp*16;
    int jg0 = j0 + jl0;
    wmma::fragment<wmma::accumulator, 16, 16, 16, float> C;
    wmma::fill_fragment(C, 0.f);
    #pragma unroll
    for (int kt = 0; kt < 8; kt++) {
        wmma::fragment<wmma::matrix_a, 16, 16, 16, __nv_bfloat16, wmma::row_major> Ah, Al;
        wmma::fragment<wmma::matrix_b, 16, 16, 16, __nv_bfloat16, wmma::col_major> Bh, Bl;
        wmma::load_matrix_sync(Ah, &AHs[kt*16], TQ_LDW);
        wmma::load_matrix_sync(Al, &ALs[kt*16], TQ_LDW);
        wmma::load_matrix_sync(Bh, &WHs[jl0*TQ_LDW + kt*16], TQ_LDW);
        wmma::load_matrix_sync(Bl, &WLs[jl0*TQ_LDW + kt*16], TQ_LDW);
        wmma::mma_sync(C, Ah, Bh, C);
        wmma::mma_sync(C, Al, Bh, C);
        wmma::mma_sync(C, Ah, Bl, C);
    }
    #pragma unroll
    for (int p = 0; p < 4; p++) {
        int i0 = p*2;
        int row = rbase + 8*((i0 >> 1) & 1);
        int col = jg0 + cbase + 8*(i0 >> 2);
        int n = n0 + row;
        float v0 = C.x[i0], v1 = C.x[i0 + 1];
        if (col < 128) {
            g_Th[n*128 + col]     = v0;
            g_Th[n*128 + col + 1] = v1;
        } else {
            int qc = col - 128;
            Qout[n*128 + qc]     = v0 + g_bsum[l*128 + qc];
            Qout[n*128 + qc + 1] = v1 + g_bsum[l*128 + qc + 1];
        }
    }
}

// ---------------- EdgeConv B part (2048 CTAs) ----------------
__global__ void edge_part_kernel() {
    int bid = blockIdx.x;
    int i = bid >> 2, ch = bid & 3;
    int c = threadIdx.x;
    unsigned bw0 = g_mask[i*16 + ch*4 + 0];
    unsigned bw1 = g_mask[i*16 + ch*4 + 1];
    unsigned bw2 = g_mask[i*16 + ch*4 + 2];
    unsigned bw3 = g_mask[i*16 + ch*4 + 3];
    const float* Th = g_Th + (size_t)(ch*128)*128 + c;
    float m0 = -3.4e38f, m1 = m0, m2 = m0, m3 = m0;
    #pragma unroll
    for (int w = 0; w < 4; w++) {
        unsigned bits = (w == 0) ? bw0 : (w == 1) ? bw1 : (w == 2) ? bw2 : bw3;
        int jb = w*32;
        #pragma unroll
        for (int b = 0; b < 32; b += 4) {
            float v0 = Th[(jb + b)*128];
            float v1 = Th[(jb + b + 1)*128];
            float v2 = Th[(jb + b + 2)*128];
            float v3 = Th[(jb + b + 3)*128];
            if (bits & (1u << b))       m0 = fmaxf(m0, v0);
            if (bits & (1u << (b + 1))) m1 = fmaxf(m1, v1);
            if (bits & (1u << (b + 2))) m2 = fmaxf(m2, v2);
            if (bits & (1u << (b + 3))) m3 = fmaxf(m3, v3);
        }
    }
    g_epart[bid*128 + c] = fmaxf(fmaxf(m0, m1), fmaxf(m2, m3));
}

// ---------------- affinity projection ----------------
__global__ void pproj_kernel(int rec, int qi) {
    __shared__ float sh[128];
    int i = blockIdx.x, c = threadIdx.x;
    float hv0, hv1;
    if (rec) {
        const float* Qin = g_Q[qi];
        int c1 = c + 64;
        float m0 = fmaxf(fmaxf(g_epart[(i*4 + 0)*128 + c], g_epart[(i*4 + 1)*128 + c]),
                         fmaxf(g_epart[(i*4 + 2)*128 + c], g_epart[(i*4 + 3)*128 + c]));
        float m1 = fmaxf(fmaxf(g_epart[(i*4 + 0)*128 + c1], g_epart[(i*4 + 1)*128 + c1]),
                         fmaxf(g_epart[(i*4 + 2)*128 + c1], g_epart[(i*4 + 3)*128 + c1]));
        hv0 = fmaxf(m0 + Qin[i*128 + c],  0.f);
        hv1 = fmaxf(m1 + Qin[i*128 + c1], 0.f);
    } else {
        hv0 = g_h[i*128 + c];
        hv1 = g_h[i*128 + 64 + c];
    }
    sh[c]      = hv0;
    sh[64 + c] = hv1;
    __syncthreads();
    ull acA = 0ULL, acB = 0ULL;
    #pragma unroll 8
    for (int k2 = 0; k2 < 64; k2 += 2) {
        fma2(acA, *(const ull*)&sh[2*k2],     *(const ull*)&g_w1p[(k2*64 + c)*2]);
        fma2(acB, *(const ull*)&sh[2*k2 + 2], *(const ull*)&g_w1p[((k2 + 1)*64 + c)*2]);
    }
    float2 pA = unpack2(acA), pB = unpack2(acB);
    g_P[i*64 + c] = (pA.x + pA.y) + (pB.x + pB.y);
}

// ---------------- pairwise head ----------------
__global__ void pair_kernel(const float* b1, const float* w2, const float* b2, float* out) {
    __shared__ float sPi[16*65], sPj[16*65], sw2[64], sb1v[64];
    int tid = threadIdx.x;
    int ib = (blockIdx.x >> 4)*16, jb = (blockIdx.x & 15)*16;
    for (int t = tid; t < 1024; t += 256) {
        int r = t >> 6, c = t & 63;
        sPi[r*65 + c] = g_P[(ib + r)*64 + c];
        sPj[r*65 + c] = g_P[(jb + r)*64 + c];
    }
    if (tid < 64) { sw2[tid] = w2[tid]; sb1v[tid] = b1[tid]; }
    __syncthreads();
    int ti = tid >> 4, tj = tid & 15;
    float sA = 0.f, sB = 0.f;
    #pragma unroll 8
    for (int c = 0; c < 64; c += 2) {
        sA += sw2[c]    *fmaxf(sPj[tj*65 + c]     - sPi[ti*65 + c]     + sb1v[c],     0.f);
        sB += sw2[c + 1]*fmaxf(sPj[tj*65 + c + 1] - sPi[ti*65 + c + 1] + sb1v[c + 1], 0.f);
    }
    out[(ib + ti)*256 + jb + tj] = sigmf(sA + sB + b2[0]);
}

// ---------------- launch ----------------
extern "C" void kernel_launch(void* const* d_in, const int* in_sizes, int n_in,
                              void* d_out, int out_size) {
    const float* det_pts   = (const float*)d_in[0];
    const float* det_boxes = (const float*)d_in[1];
    const float* trk_pts   = (const float*)d_in[2];
    const float* trk_boxes = (const float*)d_in[3];
    const int*   adj       = (const int*)  d_in[4];
    const float* pn_w1 = (const float*)d_in[5];
    const float* pn_b1 = (const float*)d_in[6];
    const float* pn_w2 = (const float*)d_in[7];
    const float* pn_b2 = (const float*)d_in[8];
    const float* pn_w3 = (const float*)d_in[9];
    const float* pn_b3 = (const float*)d_in[10];
    const float* dm_w1 = (const float*)d_in[11];
    const float* dm_b1 = (const float*)d_in[12];
    const float* dm_w2 = (const float*)d_in[13];
    const float* dm_b2 = (const float*)d_in[14];
    const float* l0_wih = (const float*)d_in[15];
    const float* l0_whh = (const float*)d_in[16];
    const float* l0_bih = (const float*)d_in[17];
    const float* l0_bhh = (const float*)d_in[18];
    const float* l1_wih = (const float*)d_in[19];
    const float* l1_whh = (const float*)d_in[20];
    const float* l1_bih = (const float*)d_in[21];
    const float* l1_bhh = (const float*)d_in[22];
    const float* gc_wt = (const float*)d_in[23];
    const float* gc_bt = (const float*)d_in[24];
    const float* gc_wp = (const float*)d_in[25];
    const float* gc_bp = (const float*)d_in[26];
    const float* er_w1 = (const float*)d_in[27];
    const float* er_b1 = (const float*)d_in[28];
    const float* er_w2 = (const float*)d_in[29];
    const float* er_b2 = (const float*)d_in[30];
    float* out = (float*)d_out;

    cudaFuncSetAttribute(mega_kernel, cudaFuncAttributeMaxDynamicSharedMemorySize,
                         MEGA_SMEM);
    cudaFuncSetAttribute(thq_wmma_kernel, cudaFuncAttributeMaxDynamicSharedMemorySize,
                         TQ_SMEM);

    mega_kernel<<<641, 256, MEGA_SMEM>>>(
        det_pts, trk_pts, pn_w1, pn_b1, pn_w2, pn_b2, pn_w3, pn_b3,
        det_boxes, dm_w1, dm_b1, dm_w2, dm_b2,
        trk_boxes, l0_wih, l0_whh, l0_bih, l0_bhh,
        l1_wih, l1_whh, l1_bih, l1_bhh,
        gc_wt, gc_bt, gc_wp, gc_bp, er_w1, adj);

    thq_wmma_kernel<<<128, 128, TQ_SMEM>>>(0, 0, 0, 0);
    edge_part_kernel<<<2048, 128>>>();
    thq_wmma_kernel<<<128, 128, TQ_SMEM>>>(1, 1, 0, 1);
    edge_part_kernel<<<2048, 128>>>();
    pproj_kernel<<<256, 64>>>(0, 0);
    pair_kernel<<<256, 256>>>(er_b1, er_w2, er_b2, out);
    thq_wmma_kernel<<<128, 128, TQ_SMEM>>>(2, 1, 1, 0);
    edge_part_kernel<<<2048, 128>>>();
    thq_wmma_kernel<<<128, 128, TQ_SMEM>>>(3, 1, 0, 1);
    edge_part_kernel<<<2048, 128>>>();
    pproj_kernel<<<256, 64>>>(1, 1);
    pair_kernel<<<256, 256>>>(er_b1, er_w2, er_b2, out + 65536);
}